// round 14
// baseline (speedup 1.0000x reference)
#include <cuda_runtime.h>
#include <math.h>

#define NC 10
#define NG 8
#define TPB 256
#define WARPS (TPB / 32)
#define QCAP 256           // gather ring capacity per warp (power of 2)
#define GC   7             // gathered classes: 0..6
#define SC   3             // streamed classes: 7..9
#define BPC  58            // blocks per gathered class
#define SB   62            // blocks per streamed class
#define GRID (GC * BPC + SC * SB)   // 592 = one full wave @4/SM

// Scratch (__device__ globals; zero-init at load; finalize resets for replays)
__device__ float g_S[NC * NG];
__device__ float g_V[NC * NG];
__device__ float g_count[NC];
__device__ unsigned g_ticket;

// Per-row accumulate: S_i += a_i;  V_i += a_i * (R - log a_i), R = sum log a_j
#define ACC(AQ, BQ)                                                             \
    {                                                                           \
        float a[NG] = {(AQ).x, (AQ).y, (AQ).z, (AQ).w,                          \
                       (BQ).x, (BQ).y, (BQ).z, (BQ).w};                         \
        float la[NG]; float R = 0.0f;                                           \
        _Pragma("unroll")                                                       \
        for (int g = 0; g < NG; ++g) { la[g] = __logf(a[g]); R += la[g]; }      \
        _Pragma("unroll")                                                       \
        for (int g = 0; g < NG; ++g) {                                          \
            s[g] += a[g];                                                       \
            v[g] = fmaf(a[g], R - la[g], v[g]);                                 \
        }                                                                       \
    }

// Weighted row (streamed path). Unmatched rows are substituted with 1.0 BEFORE
// the log (their elements may be exactly 0.0 -> -inf -> NaN otherwise); wf=0
// then contributes exactly nothing.
#define WROW(AQ, BQ, MATCH)                                                     \
    {                                                                           \
        float wf = (MATCH) ? 1.0f : 0.0f;                                       \
        float a[NG] = {(AQ).x, (AQ).y, (AQ).z, (AQ).w,                          \
                       (BQ).x, (BQ).y, (BQ).z, (BQ).w};                         \
        _Pragma("unroll")                                                       \
        for (int g = 0; g < NG; ++g) a[g] = (MATCH) ? a[g] : 1.0f;              \
        float la[NG]; float R = 0.0f;                                           \
        _Pragma("unroll")                                                       \
        for (int g = 0; g < NG; ++g) { la[g] = __logf(a[g]); R += la[g]; }      \
        _Pragma("unroll")                                                       \
        for (int g = 0; g < NG; ++g) {                                          \
            float wa = wf * a[g];                                               \
            s[g] += wa;                                                         \
            v[g] = fmaf(wa, R - la[g], v[g]);                                   \
        }                                                                       \
        cnt += wf;                                                              \
    }

// ---------------------------------------------------------------------------
// Hybrid kernel. Gather role (classes 0..GC-1): warp-compacted scan + 32B row
// gather (activation-bound, bus mostly idle). Stream role (classes GC..NC-1):
// dense sequential sweep of the class plane with mask weights (bus-bound,
// activation-cheap) — rides the idle bus cycles. Last-block ticket finalize.
__global__ __launch_bounds__(TPB) void k_all(const float* __restrict__ act,
                                             const int* __restrict__ labels,
                                             int N, float* __restrict__ out) {
    const int w    = threadIdx.x >> 5;
    const int lane = threadIdx.x & 31;
    const int nq   = N >> 2;
    const int4* lab4 = (const int4*)labels;

    __shared__ int qbuf[WARPS][QCAP];
    __shared__ float sh[2 * NG + 1];
    __shared__ bool amLast;
    __shared__ float pc[NC];

    if (threadIdx.x < 2 * NG + 1) sh[threadIdx.x] = 0.0f;
    __syncthreads();

    float s[NG] = {0,0,0,0,0,0,0,0};
    float v[NG] = {0,0,0,0,0,0,0,0};
    float cnt = 0.0f;
    int c;   // class this block contributes to

    if (blockIdx.x < GC * BPC) {
        // ================= GATHER ROLE =================
        c = blockIdx.x / BPC;
        const int b = blockIdx.x % BPC;
        const int want = c + 1;
        const size_t clsBase = (size_t)c * (size_t)N;

        unsigned head = 0, tail = 0;   // warp-uniform ring cursors
        const int gw     = b * WARPS + w;
        const int stride = BPC * WARPS * 32;
        const unsigned ltmask = (1u << lane) - 1u;

        #define BATCH32()                                                       \
            {                                                                   \
                __syncwarp();                                                   \
                int idx = qbuf[w][(head + lane) & (QCAP - 1)];                  \
                head += 32;                                                     \
                const float4* r = (const float4*)(act + (clsBase + (size_t)idx) * NG); \
                float4 aq = r[0], bq = r[1];                                    \
                ACC(aq, bq)                                                     \
            }
        #define SLOT(LV, OFF)                                                  \
            {                                                                   \
                unsigned m = __ballot_sync(0xFFFFFFFFu, (LV) == want);          \
                if ((LV) == want)                                               \
                    qbuf[w][(tail + __popc(m & ltmask)) & (QCAP - 1)] = n + (OFF); \
                tail += __popc(m);                                              \
            }

        for (int base = gw * 32; base < nq; base += stride) {
            int q = base + lane;
            int4 lb;
            if (q < nq) lb = lab4[q];
            else        { lb.x = 0; lb.y = 0; lb.z = 0; lb.w = 0; }
            int n = q << 2;
            SLOT(lb.x, 0) SLOT(lb.y, 1) SLOT(lb.z, 2) SLOT(lb.w, 3)
            while (tail - head >= 32) BATCH32()
        }
        // scalar label tail (N % 4): block 0, warp 0 of this class
        if (b == 0 && w == 0) {
            for (int nb = nq << 2; nb < N; nb += 32) {
                int n = nb + lane;
                int lv = (n < N) ? labels[n] : 0;
                unsigned m = __ballot_sync(0xFFFFFFFFu, lv == want);
                if (lv == want)
                    qbuf[w][(tail + __popc(m & ltmask)) & (QCAP - 1)] = n;
                tail += __popc(m);
                while (tail - head >= 32) BATCH32()
            }
        }
        // drain the final <32 with predication
        {
            unsigned rem = tail - head;
            __syncwarp();
            int idx = (lane < (int)rem) ? qbuf[w][(head + lane) & (QCAP - 1)] : 0;
            if (lane < (int)rem) {
                const float4* r = (const float4*)(act + (clsBase + (size_t)idx) * NG);
                float4 aq = r[0], bq = r[1];
                ACC(aq, bq)
            }
        }
        #undef SLOT
        #undef BATCH32
        cnt = (lane == 0) ? (float)tail : 0.0f;   // warp-uniform count -> lane 0
    } else {
        // ================= STREAM ROLE =================
        const int sb = blockIdx.x - GC * BPC;
        c = GC + sb / SB;
        const int b = sb % SB;
        const int want = c + 1;
        const size_t clsBase = (size_t)c * (size_t)N;

        for (int q = b * TPB + threadIdx.x; q < nq; q += SB * TPB) {
            int4 lb = lab4[q];
            const float4* base = (const float4*)(act + clsBase + ((size_t)q << 5));
            // 4 consecutive rows = one 128B line per thread, coalesced per warp
            float4 x0 = __ldcs(base + 0), y0 = __ldcs(base + 1);
            float4 x1 = __ldcs(base + 2), y1 = __ldcs(base + 3);
            float4 x2 = __ldcs(base + 4), y2 = __ldcs(base + 5);
            float4 x3 = __ldcs(base + 6), y3 = __ldcs(base + 7);
            WROW(x0, y0, lb.x == want)
            WROW(x1, y1, lb.y == want)
            WROW(x2, y2, lb.z == want)
            WROW(x3, y3, lb.w == want)
        }
        // scalar row tail (N % 4): block 0 of this class, per-lane predicated
        if (b == 0 && w == 0) {
            int n = (nq << 2) + lane;
            if (n < N) {
                bool match = (labels[n] == want);
                const float4* r = (const float4*)(act + (clsBase + (size_t)n) * NG);
                float4 aq = match ? r[0] : make_float4(1, 1, 1, 1);
                float4 bq = match ? r[1] : make_float4(1, 1, 1, 1);
                WROW(aq, bq, match)
            }
        }
    }

    // ---- common epilogue: warp reduce 17 values, block reduce, global atomics
    #pragma unroll
    for (int o = 16; o > 0; o >>= 1) {
        #pragma unroll
        for (int g = 0; g < NG; ++g) {
            s[g] += __shfl_down_sync(0xFFFFFFFFu, s[g], o);
            v[g] += __shfl_down_sync(0xFFFFFFFFu, v[g], o);
        }
        cnt += __shfl_down_sync(0xFFFFFFFFu, cnt, o);
    }
    if (lane == 0) {
        #pragma unroll
        for (int g = 0; g < NG; ++g) {
            atomicAdd(&sh[g], s[g]);
            atomicAdd(&sh[NG + g], v[g]);
        }
        atomicAdd(&sh[2 * NG], cnt);
    }
    __syncthreads();
    if (threadIdx.x < NG) {
        atomicAdd(&g_S[c * NG + threadIdx.x], sh[threadIdx.x]);
        atomicAdd(&g_V[c * NG + threadIdx.x], sh[NG + threadIdx.x]);
    }
    if (threadIdx.x == 2 * NG) atomicAdd(&g_count[c], sh[2 * NG]);

    // ---- last-block finalize ----
    __threadfence();
    if (threadIdx.x == 0)
        amLast = (atomicAdd(&g_ticket, 1u) == (unsigned)(GRID - 1));
    __syncthreads();
    if (!amLast) return;

    int t = threadIdx.x;
    if (t < NC) pc[t] = 0.0f;
    __syncthreads();
    if (t < NC * NG) {
        float S = __ldcg(&g_S[t]);
        float V = __ldcg(&g_V[t]);
        float term = V / S - (float)(NG - 1) * logf(S);
        atomicAdd(&pc[t / NG], term);
    }
    __syncthreads();
    if (t == 0) {
        float num = 0.0f, vcnt = 0.0f;
        #pragma unroll
        for (int cc = 0; cc < NC; ++cc) {
            float cn = __ldcg(&g_count[cc]);
            if (cn >= 2.0f) { num += pc[cc]; vcnt += 1.0f; }
        }
        out[0] = num / (vcnt * (float)(NG * (NG - 1)));
        g_ticket = 0;                               // reset for next replay
    }
    __syncthreads();
    if (t < NC * NG) { g_S[t] = 0.0f; g_V[t] = 0.0f; }
    if (t < NC) g_count[t] = 0.0f;
}

// ---------------------------------------------------------------------------
extern "C" void kernel_launch(void* const* d_in, const int* in_sizes, int n_in,
                              void* d_out, int out_size) {
    const float* act  = (const float*)d_in[0];   // [C, N, G] float32
    const int* labels = (const int*)d_in[1];     // [N] int32
    const int N = in_sizes[1];

    k_all<<<GRID, TPB>>>(act, labels, N, (float*)d_out);
}

// round 15
// speedup vs baseline: 1.7254x; 1.7254x over previous
#include <cuda_runtime.h>
#include <math.h>

#define NC 10
#define NG 8
#define TPB 256
#define WARPS (TPB / 32)
#define QCAP 256           // ring capacity per warp (power of 2)
#define BPC 59             // blocks per class -> grid 590 = one full wave @4/SM
#define GRID (NC * BPC)

// Scratch (__device__ globals; zero-init at load; finalize resets for replays)
__device__ float g_S[NC * NG];
__device__ float g_V[NC * NG];
__device__ float g_count[NC];
__device__ unsigned g_ticket;

// Per-row accumulate: S_i += a_i;  V_i += a_i * (R - log a_i), R = sum log a_j
#define ACC(AQ, BQ)                                                             \
    {                                                                           \
        float a[NG] = {(AQ).x, (AQ).y, (AQ).z, (AQ).w,                          \
                       (BQ).x, (BQ).y, (BQ).z, (BQ).w};                         \
        float la[NG]; float R = 0.0f;                                           \
        _Pragma("unroll")                                                       \
        for (int g = 0; g < NG; ++g) { la[g] = __logf(a[g]); R += la[g]; }      \
        _Pragma("unroll")                                                       \
        for (int g = 0; g < NG; ++g) {                                          \
            s[g] += a[g];                                                       \
            v[g] = fmaf(a[g], R - la[g], v[g]);                                 \
        }                                                                       \
    }

// ---------------------------------------------------------------------------
// Single fused kernel: warp-compacted class scan + gather + last-block
// finalize. Each block owns ONE class. Warps scan labels (int4, warp-uniform
// bounds), ballot-compact matched row indices into a shared ring, and drain in
// full 32-lane batches (unconditional 32B row gathers, full-utilization
// logf/FMA). This design sits at the measured DRAM scattered-line floor
// (~53 MB / ~24 G-lines/s); six alternative memory structures tested no better.
__global__ __launch_bounds__(TPB, 4) void k_all(const float* __restrict__ act,
                                                const int* __restrict__ labels,
                                                int N, float* __restrict__ out) {
    const int c    = blockIdx.x / BPC;
    const int b    = blockIdx.x % BPC;
    const int w    = threadIdx.x >> 5;
    const int lane = threadIdx.x & 31;
    const int want = c + 1;
    const size_t clsBase = (size_t)c * (size_t)N;

    __shared__ int qbuf[WARPS][QCAP];
    __shared__ float sh[2 * NG + 1];
    __shared__ bool amLast;
    __shared__ float pc[NC];

    if (threadIdx.x < 2 * NG + 1) sh[threadIdx.x] = 0.0f;
    __syncthreads();

    float s[NG] = {0,0,0,0,0,0,0,0};
    float v[NG] = {0,0,0,0,0,0,0,0};

    unsigned head = 0, tail = 0;   // warp-uniform ring cursors

    const int nq = N >> 2;
    const int4* lab4 = (const int4*)labels;
    const int gw     = b * WARPS + w;
    const int stride = BPC * WARPS * 32;
    const unsigned ltmask = (1u << lane) - 1u;

    #define BATCH32()                                                           \
        {                                                                       \
            __syncwarp();                                                       \
            int idx = qbuf[w][(head + lane) & (QCAP - 1)];                      \
            head += 32;                                                         \
            const float4* r = (const float4*)(act + (clsBase + (size_t)idx) * NG); \
            float4 aq = r[0], bq = r[1];                                        \
            ACC(aq, bq)                                                         \
        }

    #define SLOT(LV, OFF)                                                      \
        {                                                                       \
            unsigned m = __ballot_sync(0xFFFFFFFFu, (LV) == want);              \
            if ((LV) == want)                                                   \
                qbuf[w][(tail + __popc(m & ltmask)) & (QCAP - 1)] = n + (OFF);  \
            tail += __popc(m);                                                  \
        }

    // Warp-uniform outer loop: 'base' is identical across the warp.
    for (int base = gw * 32; base < nq; base += stride) {
        int q = base + lane;
        int4 lb;
        if (q < nq) lb = lab4[q];
        else        { lb.x = 0; lb.y = 0; lb.z = 0; lb.w = 0; }
        int n = q << 2;
        SLOT(lb.x, 0) SLOT(lb.y, 1) SLOT(lb.z, 2) SLOT(lb.w, 3)
        while (tail - head >= 32) BATCH32()
    }

    // Scalar tail of labels (N % 4): warp 0 of block 0 per class, uniform loop.
    if (b == 0 && w == 0) {
        int tstart = nq << 2;
        for (int nb = tstart; nb < N; nb += 32) {
            int n = nb + lane;
            int lv = (n < N) ? labels[n] : 0;
            unsigned m = __ballot_sync(0xFFFFFFFFu, lv == want);
            if (lv == want)
                qbuf[w][(tail + __popc(m & ltmask)) & (QCAP - 1)] = n;
            tail += __popc(m);
            while (tail - head >= 32) BATCH32()
        }
    }

    // Drain the final <32 with predication (full warp executes).
    {
        unsigned rem = tail - head;
        __syncwarp();
        int idx = (lane < (int)rem) ? qbuf[w][(head + lane) & (QCAP - 1)] : 0;
        if (lane < (int)rem) {
            const float4* r = (const float4*)(act + (clsBase + (size_t)idx) * NG);
            float4 aq = r[0], bq = r[1];
            ACC(aq, bq)
        }
    }
    #undef SLOT
    #undef BATCH32

    float cnt = (float)tail;   // warp-uniform: rows this warp enqueued

    // warp tree-reduce 16 values (all lanes alive here)
    #pragma unroll
    for (int o = 16; o > 0; o >>= 1) {
        #pragma unroll
        for (int g = 0; g < NG; ++g) {
            s[g] += __shfl_down_sync(0xFFFFFFFFu, s[g], o);
            v[g] += __shfl_down_sync(0xFFFFFFFFu, v[g], o);
        }
    }

    if (lane == 0) {
        #pragma unroll
        for (int g = 0; g < NG; ++g) {
            atomicAdd(&sh[g], s[g]);
            atomicAdd(&sh[NG + g], v[g]);
        }
        atomicAdd(&sh[2 * NG], cnt);
    }
    __syncthreads();
    if (threadIdx.x < NG) {
        atomicAdd(&g_S[c * NG + threadIdx.x], sh[threadIdx.x]);
        atomicAdd(&g_V[c * NG + threadIdx.x], sh[NG + threadIdx.x]);
    }
    if (threadIdx.x == 2 * NG) atomicAdd(&g_count[c], sh[2 * NG]);

    // ---- last-block finalize ----
    __threadfence();
    if (threadIdx.x == 0)
        amLast = (atomicAdd(&g_ticket, 1u) == (unsigned)(GRID - 1));
    __syncthreads();
    if (!amLast) return;

    int t = threadIdx.x;
    if (t < NC) pc[t] = 0.0f;
    __syncthreads();
    if (t < NC * NG) {
        float S = __ldcg(&g_S[t]);
        float V = __ldcg(&g_V[t]);
        float term = V / S - (float)(NG - 1) * logf(S);
        atomicAdd(&pc[t / NG], term);
    }
    __syncthreads();
    if (t == 0) {
        float num = 0.0f, vcnt = 0.0f;
        #pragma unroll
        for (int cc = 0; cc < NC; ++cc) {
            float cn = __ldcg(&g_count[cc]);
            if (cn >= 2.0f) { num += pc[cc]; vcnt += 1.0f; }
        }
        out[0] = num / (vcnt * (float)(NG * (NG - 1)));
        g_ticket = 0;                               // reset for next replay
    }
    __syncthreads();
    if (t < NC * NG) { g_S[t] = 0.0f; g_V[t] = 0.0f; }
    if (t < NC) g_count[t] = 0.0f;
}

// ---------------------------------------------------------------------------
extern "C" void kernel_launch(void* const* d_in, const int* in_sizes, int n_in,
                              void* d_out, int out_size) {
    const float* act  = (const float*)d_in[0];   // [C, N, G] float32
    const int* labels = (const int*)d_in[1];     // [N] int32
    const int N = in_sizes[1];

    k_all<<<GRID, TPB>>>(act, labels, N, (float*)d_out);
}

// round 16
// speedup vs baseline: 1.7287x; 1.0019x over previous
#include <cuda_runtime.h>
#include <math.h>

#define NC 10
#define NG 8
#define TPB 256
#define WARPS (TPB / 32)
#define QCAP 256           // ring capacity per warp (power of 2)
#define BPC 59             // blocks per class -> grid 590 = one full wave @4/SM
#define GRID (NC * BPC)

// Scratch (__device__ globals; zero-init at load; finalize resets for replays)
__device__ float g_S[NC * NG];
__device__ float g_V[NC * NG];
__device__ float g_count[NC];
__device__ unsigned g_ticket;

// Per-row accumulate: S_i += a_i;  V_i += a_i * (R - log a_i), R = sum log a_j
#define ACC(AQ, BQ)                                                             \
    {                                                                           \
        float a[NG] = {(AQ).x, (AQ).y, (AQ).z, (AQ).w,                          \
                       (BQ).x, (BQ).y, (BQ).z, (BQ).w};                         \
        float la[NG]; float R = 0.0f;                                           \
        _Pragma("unroll")                                                       \
        for (int g = 0; g < NG; ++g) { la[g] = __logf(a[g]); R += la[g]; }      \
        _Pragma("unroll")                                                       \
        for (int g = 0; g < NG; ++g) {                                          \
            s[g] += a[g];                                                       \
            v[g] = fmaf(a[g], R - la[g], v[g]);                                 \
        }                                                                       \
    }

// ---------------------------------------------------------------------------
// Single fused kernel: warp-compacted class scan + gather + last-block
// finalize. Each block owns ONE class. Warps scan labels (int4, warp-uniform
// bounds), ballot-compact matched row indices into a shared ring, and drain in
// full 32-lane batches (unconditional 32B row gathers, full-utilization
// logf/FMA). This design sits at the measured DRAM scattered-line floor
// (~53 MB / ~24 G-lines/s); six alternative memory structures tested no better.
__global__ __launch_bounds__(TPB, 4) void k_all(const float* __restrict__ act,
                                                const int* __restrict__ labels,
                                                int N, float* __restrict__ out) {
    const int c    = blockIdx.x / BPC;
    const int b    = blockIdx.x % BPC;
    const int w    = threadIdx.x >> 5;
    const int lane = threadIdx.x & 31;
    const int want = c + 1;
    const size_t clsBase = (size_t)c * (size_t)N;

    __shared__ int qbuf[WARPS][QCAP];
    __shared__ float sh[2 * NG + 1];
    __shared__ bool amLast;
    __shared__ float pc[NC];

    if (threadIdx.x < 2 * NG + 1) sh[threadIdx.x] = 0.0f;
    __syncthreads();

    float s[NG] = {0,0,0,0,0,0,0,0};
    float v[NG] = {0,0,0,0,0,0,0,0};

    unsigned head = 0, tail = 0;   // warp-uniform ring cursors

    const int nq = N >> 2;
    const int4* lab4 = (const int4*)labels;
    const int gw     = b * WARPS + w;
    const int stride = BPC * WARPS * 32;
    const unsigned ltmask = (1u << lane) - 1u;

    #define BATCH32()                                                           \
        {                                                                       \
            __syncwarp();                                                       \
            int idx = qbuf[w][(head + lane) & (QCAP - 1)];                      \
            head += 32;                                                         \
            const float4* r = (const float4*)(act + (clsBase + (size_t)idx) * NG); \
            float4 aq = r[0], bq = r[1];                                        \
            ACC(aq, bq)                                                         \
        }

    #define SLOT(LV, OFF)                                                      \
        {                                                                       \
            unsigned m = __ballot_sync(0xFFFFFFFFu, (LV) == want);              \
            if ((LV) == want)                                                   \
                qbuf[w][(tail + __popc(m & ltmask)) & (QCAP - 1)] = n + (OFF);  \
            tail += __popc(m);                                                  \
        }

    // Warp-uniform outer loop: 'base' is identical across the warp.
    for (int base = gw * 32; base < nq; base += stride) {
        int q = base + lane;
        int4 lb;
        if (q < nq) lb = lab4[q];
        else        { lb.x = 0; lb.y = 0; lb.z = 0; lb.w = 0; }
        int n = q << 2;
        SLOT(lb.x, 0) SLOT(lb.y, 1) SLOT(lb.z, 2) SLOT(lb.w, 3)
        while (tail - head >= 32) BATCH32()
    }

    // Scalar tail of labels (N % 4): warp 0 of block 0 per class, uniform loop.
    if (b == 0 && w == 0) {
        int tstart = nq << 2;
        for (int nb = tstart; nb < N; nb += 32) {
            int n = nb + lane;
            int lv = (n < N) ? labels[n] : 0;
            unsigned m = __ballot_sync(0xFFFFFFFFu, lv == want);
            if (lv == want)
                qbuf[w][(tail + __popc(m & ltmask)) & (QCAP - 1)] = n;
            tail += __popc(m);
            while (tail - head >= 32) BATCH32()
        }
    }

    // Drain the final <32 with predication (full warp executes).
    {
        unsigned rem = tail - head;
        __syncwarp();
        int idx = (lane < (int)rem) ? qbuf[w][(head + lane) & (QCAP - 1)] : 0;
        if (lane < (int)rem) {
            const float4* r = (const float4*)(act + (clsBase + (size_t)idx) * NG);
            float4 aq = r[0], bq = r[1];
            ACC(aq, bq)
        }
    }
    #undef SLOT
    #undef BATCH32

    float cnt = (float)tail;   // warp-uniform: rows this warp enqueued

    // warp tree-reduce 16 values (all lanes alive here)
    #pragma unroll
    for (int o = 16; o > 0; o >>= 1) {
        #pragma unroll
        for (int g = 0; g < NG; ++g) {
            s[g] += __shfl_down_sync(0xFFFFFFFFu, s[g], o);
            v[g] += __shfl_down_sync(0xFFFFFFFFu, v[g], o);
        }
    }

    if (lane == 0) {
        #pragma unroll
        for (int g = 0; g < NG; ++g) {
            atomicAdd(&sh[g], s[g]);
            atomicAdd(&sh[NG + g], v[g]);
        }
        atomicAdd(&sh[2 * NG], cnt);
    }
    __syncthreads();
    if (threadIdx.x < NG) {
        atomicAdd(&g_S[c * NG + threadIdx.x], sh[threadIdx.x]);
        atomicAdd(&g_V[c * NG + threadIdx.x], sh[NG + threadIdx.x]);
    }
    if (threadIdx.x == 2 * NG) atomicAdd(&g_count[c], sh[2 * NG]);

    // ---- last-block finalize ----
    __threadfence();
    if (threadIdx.x == 0)
        amLast = (atomicAdd(&g_ticket, 1u) == (unsigned)(GRID - 1));
    __syncthreads();
    if (!amLast) return;

    int t = threadIdx.x;
    if (t < NC) pc[t] = 0.0f;
    __syncthreads();
    if (t < NC * NG) {
        float S = __ldcg(&g_S[t]);
        float V = __ldcg(&g_V[t]);
        float term = V / S - (float)(NG - 1) * logf(S);
        atomicAdd(&pc[t / NG], term);
    }
    __syncthreads();
    if (t == 0) {
        float num = 0.0f, vcnt = 0.0f;
        #pragma unroll
        for (int cc = 0; cc < NC; ++cc) {
            float cn = __ldcg(&g_count[cc]);
            if (cn >= 2.0f) { num += pc[cc]; vcnt += 1.0f; }
        }
        out[0] = num / (vcnt * (float)(NG * (NG - 1)));
        g_ticket = 0;                               // reset for next replay
    }
    __syncthreads();
    if (t < NC * NG) { g_S[t] = 0.0f; g_V[t] = 0.0f; }
    if (t < NC) g_count[t] = 0.0f;
}

// ---------------------------------------------------------------------------
extern "C" void kernel_launch(void* const* d_in, const int* in_sizes, int n_in,
                              void* d_out, int out_size) {
    const float* act  = (const float*)d_in[0];   // [C, N, G] float32
    const int* labels = (const int*)d_in[1];     // [N] int32
    const int N = in_sizes[1];

    k_all<<<GRID, TPB>>>(act, labels, N, (float*)d_out);
}